// round 3
// baseline (speedup 1.0000x reference)
#include <cuda_runtime.h>
#include <stdint.h>

#define DIM   64
#define MAX_N 150016           // 100000 users + 50000 items, padded
#define MAX_E 1300000          // actual E = 1,200,000 (incl. flipped copy)

// ---------------------------------------------------------------------------
// Scratch: __device__ globals only (no allocations allowed anywhere).
// ---------------------------------------------------------------------------
__device__ float g_bufA[MAX_N * DIM];   // ping
__device__ float g_bufB[MAX_N * DIM];   // pong
__device__ float g_dinv[MAX_N];         // deg^{-1/2}
__device__ int   g_counts[MAX_N];       // in-degree histogram (== out-degree; list is symmetric)
__device__ int   g_offsets[MAX_N + 1];  // CSR row pointers (by dst)
__device__ int   g_pos[MAX_N];          // scatter cursors
__device__ int   g_src[MAX_E];          // CSR: source node per slot
__device__ float g_norm[MAX_E];         // CSR: edge norm per slot

// ---------------------------------------------------------------------------
// 1) histogram of destinations (int atomics, spread addresses)
// ---------------------------------------------------------------------------
__global__ void zero_counts_kernel(int n) {
    int i = blockIdx.x * blockDim.x + threadIdx.x;
    if (i < n) g_counts[i] = 0;
}

__global__ void count_kernel(const int* __restrict__ edge, int E) {
    int e = blockIdx.x * blockDim.x + threadIdx.x;
    if (e < E) atomicAdd(&g_counts[edge[E + e]], 1);
}

// deg^{-1/2}. Symmetric edge list => row-degree == col-degree == counts.
__global__ void dinv_kernel(int n) {
    int i = blockIdx.x * blockDim.x + threadIdx.x;
    if (i < n) g_dinv[i] = rsqrtf((float)g_counts[i]);  // inf on isolated nodes: never used
}

// ---------------------------------------------------------------------------
// 2) single-block exclusive scan of counts -> offsets (and pos copy)
// ---------------------------------------------------------------------------
__global__ void scan_kernel(int n, int E) {
    __shared__ int ssum[1024];
    const int t = threadIdx.x;
    const int chunk = (n + 1023) >> 10;
    const int lo = t * chunk;
    const int hi = min(lo + chunk, n);

    int s = 0;
    for (int i = lo; i < hi; i++) s += g_counts[i];
    ssum[t] = s;
    __syncthreads();

    // Hillis-Steele inclusive scan over 1024 partials
    for (int off = 1; off < 1024; off <<= 1) {
        int v = 0;
        if (t >= off) v = ssum[t - off];
        __syncthreads();
        if (t >= off) ssum[t] += v;
        __syncthreads();
    }

    int prefix = (t == 0) ? 0 : ssum[t - 1];
    for (int i = lo; i < hi; i++) {
        g_offsets[i] = prefix;
        g_pos[i]     = prefix;
        prefix += g_counts[i];
    }
    if (t == 1023) g_offsets[n] = E;
}

// ---------------------------------------------------------------------------
// 3) scatter edges into CSR slots; precompute norm per slot
// ---------------------------------------------------------------------------
__global__ void fill_kernel(const int* __restrict__ edge, int E) {
    int e = blockIdx.x * blockDim.x + threadIdx.x;
    if (e >= E) return;
    int r = edge[e];
    int c = edge[E + e];
    int slot = atomicAdd(&g_pos[c], 1);
    g_src[slot]  = r;
    g_norm[slot] = g_dinv[r] * g_dinv[c];
}

// ---------------------------------------------------------------------------
// 4) init: A = concat(user_emb, item_emb); out = 0.25 * A
// ---------------------------------------------------------------------------
__global__ void init_kernel(const float* __restrict__ ue, const float* __restrict__ ie,
                            int nu_elems, int total, float* __restrict__ out) {
    int i = blockIdx.x * blockDim.x + threadIdx.x;
    if (i < total) {
        float v = (i < nu_elems) ? ue[i] : ie[i - nu_elems];
        g_bufA[i] = v;
        out[i]    = 0.25f * v;
    }
}

// ---------------------------------------------------------------------------
// 5) pull pass: Y[n] = sum_{k in csr(n)} norm[k] * X[src[k]];  out[n] += 0.25*Y[n]
//    16 threads (half-warp) per node, one float4 lane each -> each edge gather
//    is a contiguous 256B row read; Y/out writes fully coalesced. No atomics.
// ---------------------------------------------------------------------------
template <bool A_TO_B>
__global__ __launch_bounds__(256)
void pull_kernel(int N, float* __restrict__ out) {
    int t = blockIdx.x * blockDim.x + threadIdx.x;
    int node = t >> 4;
    if (node >= N) return;
    int c = (t & 15) << 2;

    const float* __restrict__ X = A_TO_B ? g_bufA : g_bufB;
    float*       __restrict__ Y = A_TO_B ? g_bufB : g_bufA;

    const int beg = g_offsets[node];
    const int end = g_offsets[node + 1];

    float ax = 0.f, ay = 0.f, az = 0.f, aw = 0.f;
    for (int k = beg; k < end; k++) {
        int   s  = g_src[k];
        float nm = g_norm[k];
        float4 v = *reinterpret_cast<const float4*>(X + (size_t)s * DIM + c);
        ax = fmaf(nm, v.x, ax);
        ay = fmaf(nm, v.y, ay);
        az = fmaf(nm, v.z, az);
        aw = fmaf(nm, v.w, aw);
    }

    float4 r; r.x = ax; r.y = ay; r.z = az; r.w = aw;
    *reinterpret_cast<float4*>(Y + (size_t)node * DIM + c) = r;

    float4* op = reinterpret_cast<float4*>(out + (size_t)node * DIM + c);
    float4 ov = *op;
    ov.x += 0.25f * ax;
    ov.y += 0.25f * ay;
    ov.z += 0.25f * az;
    ov.w += 0.25f * aw;
    *op = ov;
}

// ---------------------------------------------------------------------------
// kernel_launch
// inputs: [0] user_emb f32 [100000*64], [1] item_emb f32 [50000*64],
//         [2] edge_index int32 [2 * 1200000]  (JAX x64 disabled -> int32)
// output: f32 [150000*64]
// ---------------------------------------------------------------------------
extern "C" void kernel_launch(void* const* d_in, const int* in_sizes, int n_in,
                              void* d_out, int out_size) {
    const float* user_emb = (const float*)d_in[0];
    const float* item_emb = (const float*)d_in[1];
    const int*   edge     = (const int*)d_in[2];
    float*       out      = (float*)d_out;

    const int nu_elems = in_sizes[0];
    const int ni_elems = in_sizes[1];
    const int E        = in_sizes[2] / 2;
    const int N        = nu_elems / DIM + ni_elems / DIM;
    const int total    = N * DIM;

    const int TB = 256;
    const int nblk  = (N + TB - 1) / TB;
    const int eblk  = (E + TB - 1) / TB;
    const int tblk  = (total + TB - 1) / TB;
    const int pullb = (N * 16 + TB - 1) / TB;

    // CSR build (by destination)
    zero_counts_kernel<<<nblk, TB>>>(N);
    count_kernel<<<eblk, TB>>>(edge, E);
    dinv_kernel<<<nblk, TB>>>(N);
    scan_kernel<<<1, 1024>>>(N, E);
    fill_kernel<<<eblk, TB>>>(edge, E);

    // x0 and pooled output init
    init_kernel<<<tblk, TB>>>(user_emb, item_emb, nu_elems, total, out);

    // 3 propagation layers, out accumulation fused
    pull_kernel<true ><<<pullb, TB>>>(N, out);   // A -> B
    pull_kernel<false><<<pullb, TB>>>(N, out);   // B -> A
    pull_kernel<true ><<<pullb, TB>>>(N, out);   // A -> B
}

// round 4
// speedup vs baseline: 1.7005x; 1.7005x over previous
#include <cuda_runtime.h>
#include <stdint.h>

#define DIM   64
#define MAX_N 150016           // 100000 users + 50000 items, padded
#define MAX_E 1300000          // actual E = 1,200,000 (incl. flipped copy)

#define SCAN_TB    256
#define SCAN_ITEMS 8           // 2048 elements per block
#define SCAN_CHUNK (SCAN_TB * SCAN_ITEMS)
#define MAX_SCAN_BLOCKS 512

// ---------------------------------------------------------------------------
// Scratch: __device__ globals only (no allocations allowed anywhere).
// ---------------------------------------------------------------------------
__device__ float g_bufA[MAX_N * DIM];   // ping
__device__ float g_bufB[MAX_N * DIM];   // pong
__device__ float g_dinv[MAX_N];         // deg^{-1/2}
__device__ int   g_counts[MAX_N];       // in-degree histogram (== out-degree; list symmetric)
__device__ int   g_offsets[MAX_N + 1];  // CSR row pointers (by dst)
__device__ int   g_pos[MAX_N];          // scatter cursors
__device__ int   g_src[MAX_E];          // CSR: source node per slot
__device__ float g_norm[MAX_E];         // CSR: edge norm per slot
__device__ int   g_blocksums[MAX_SCAN_BLOCKS];
__device__ int   g_blockoffs[MAX_SCAN_BLOCKS];

// ---------------------------------------------------------------------------
// 1) histogram of destinations (int atomics, spread addresses)
// ---------------------------------------------------------------------------
__global__ void zero_counts_kernel(int n) {
    int i = blockIdx.x * blockDim.x + threadIdx.x;
    if (i < n) g_counts[i] = 0;
}

__global__ void count_kernel(const int* __restrict__ edge, int E) {
    int e = blockIdx.x * blockDim.x + threadIdx.x;
    if (e < E) atomicAdd(&g_counts[edge[E + e]], 1);
}

// deg^{-1/2}. Symmetric edge list => row-degree == col-degree == counts.
__global__ void dinv_kernel(int n) {
    int i = blockIdx.x * blockDim.x + threadIdx.x;
    if (i < n) g_dinv[i] = rsqrtf((float)g_counts[i]);  // inf on isolated nodes: never used
}

// ---------------------------------------------------------------------------
// 2) multi-block exclusive scan of counts -> offsets (3 phases)
// ---------------------------------------------------------------------------
// Phase A: per-block sum of a 2048-element chunk.
__global__ __launch_bounds__(SCAN_TB)
void scan_partial_kernel(int n) {
    __shared__ int warp_sums[SCAN_TB / 32];
    const int base = blockIdx.x * SCAN_CHUNK;
    const int t = threadIdx.x;

    int s = 0;
    #pragma unroll
    for (int i = 0; i < SCAN_ITEMS; i++) {
        int idx = base + i * SCAN_TB + t;       // coalesced
        if (idx < n) s += g_counts[idx];
    }
    // warp reduce
    #pragma unroll
    for (int o = 16; o > 0; o >>= 1) s += __shfl_down_sync(0xffffffffu, s, o);
    if ((t & 31) == 0) warp_sums[t >> 5] = s;
    __syncthreads();
    if (t < SCAN_TB / 32) {
        int v = warp_sums[t];
        #pragma unroll
        for (int o = SCAN_TB / 64; o > 0; o >>= 1) v += __shfl_down_sync(0xffffffffu, v, o);
        if (t == 0) g_blocksums[blockIdx.x] = v;
    }
}

// Phase B: single-block exclusive scan over block sums (nb <= 512).
__global__ __launch_bounds__(MAX_SCAN_BLOCKS)
void scan_blocksums_kernel(int nb, int n, int E) {
    __shared__ int sh[MAX_SCAN_BLOCKS];
    const int t = threadIdx.x;
    sh[t] = (t < nb) ? g_blocksums[t] : 0;
    __syncthreads();
    // Hillis-Steele inclusive
    #pragma unroll
    for (int off = 1; off < MAX_SCAN_BLOCKS; off <<= 1) {
        int v = (t >= off) ? sh[t - off] : 0;
        __syncthreads();
        sh[t] += v;
        __syncthreads();
    }
    if (t < nb) g_blockoffs[t] = (t == 0) ? 0 : sh[t - 1];
    if (t == 0) g_offsets[n] = E;
}

// Phase C: per-block local exclusive scan + block offset -> offsets/pos.
// Thread t owns the contiguous sub-chunk [base + t*8, base + t*8 + 8).
__global__ __launch_bounds__(SCAN_TB)
void scan_write_kernel(int n) {
    __shared__ int thread_sums[SCAN_TB];
    const int base = blockIdx.x * SCAN_CHUNK;
    const int t = threadIdx.x;
    const int lo = base + t * SCAN_ITEMS;

    int c[SCAN_ITEMS];
    int s = 0;
    #pragma unroll
    for (int i = 0; i < SCAN_ITEMS; i++) {
        int idx = lo + i;
        c[i] = (idx < n) ? g_counts[idx] : 0;
        s += c[i];
    }
    thread_sums[t] = s;
    __syncthreads();
    // Hillis-Steele inclusive over 256 thread sums
    #pragma unroll
    for (int off = 1; off < SCAN_TB; off <<= 1) {
        int v = (t >= off) ? thread_sums[t - off] : 0;
        __syncthreads();
        thread_sums[t] += v;
        __syncthreads();
    }
    int prefix = g_blockoffs[blockIdx.x] + ((t == 0) ? 0 : thread_sums[t - 1]);
    #pragma unroll
    for (int i = 0; i < SCAN_ITEMS; i++) {
        int idx = lo + i;
        if (idx < n) {
            g_offsets[idx] = prefix;
            g_pos[idx]     = prefix;
            prefix += c[i];
        }
    }
}

// ---------------------------------------------------------------------------
// 3) scatter edges into CSR slots; precompute norm per slot
// ---------------------------------------------------------------------------
__global__ void fill_kernel(const int* __restrict__ edge, int E) {
    int e = blockIdx.x * blockDim.x + threadIdx.x;
    if (e >= E) return;
    int r = edge[e];
    int c = edge[E + e];
    int slot = atomicAdd(&g_pos[c], 1);
    g_src[slot]  = r;
    g_norm[slot] = g_dinv[r] * g_dinv[c];
}

// ---------------------------------------------------------------------------
// 4) init: A = concat(user_emb, item_emb); out = 0.25 * A
// ---------------------------------------------------------------------------
__global__ void init_kernel(const float* __restrict__ ue, const float* __restrict__ ie,
                            int nu_elems, int total, float* __restrict__ out) {
    int i = blockIdx.x * blockDim.x + threadIdx.x;
    if (i < total) {
        float v = (i < nu_elems) ? ue[i] : ie[i - nu_elems];
        g_bufA[i] = v;
        out[i]    = 0.25f * v;
    }
}

// ---------------------------------------------------------------------------
// 5) pull pass: Y[n] = sum_{k in csr(n)} norm[k] * X[src[k]];  out[n] += 0.25*Y[n]
//    16 threads (half-warp) per node, one float4 lane each. No atomics.
//    (src, norm) prefetched one iteration ahead for extra MLP.
// ---------------------------------------------------------------------------
template <bool A_TO_B>
__global__ __launch_bounds__(256)
void pull_kernel(int N, float* __restrict__ out) {
    int t = blockIdx.x * blockDim.x + threadIdx.x;
    int node = t >> 4;
    if (node >= N) return;
    int c = (t & 15) << 2;

    const float* __restrict__ X = A_TO_B ? g_bufA : g_bufB;
    float*       __restrict__ Y = A_TO_B ? g_bufB : g_bufA;

    const int beg = g_offsets[node];
    const int end = g_offsets[node + 1];

    float ax = 0.f, ay = 0.f, az = 0.f, aw = 0.f;
    if (beg < end) {
        int   s  = g_src[beg];
        float nm = g_norm[beg];
        for (int k = beg; k + 1 < end; k++) {
            int   s2  = g_src[k + 1];          // prefetch next edge
            float nm2 = g_norm[k + 1];
            float4 v = *reinterpret_cast<const float4*>(X + (size_t)s * DIM + c);
            ax = fmaf(nm, v.x, ax);
            ay = fmaf(nm, v.y, ay);
            az = fmaf(nm, v.z, az);
            aw = fmaf(nm, v.w, aw);
            s = s2; nm = nm2;
        }
        float4 v = *reinterpret_cast<const float4*>(X + (size_t)s * DIM + c);
        ax = fmaf(nm, v.x, ax);
        ay = fmaf(nm, v.y, ay);
        az = fmaf(nm, v.z, az);
        aw = fmaf(nm, v.w, aw);
    }

    float4 r; r.x = ax; r.y = ay; r.z = az; r.w = aw;
    *reinterpret_cast<float4*>(Y + (size_t)node * DIM + c) = r;

    float4* op = reinterpret_cast<float4*>(out + (size_t)node * DIM + c);
    float4 ov = *op;
    ov.x += 0.25f * ax;
    ov.y += 0.25f * ay;
    ov.z += 0.25f * az;
    ov.w += 0.25f * aw;
    *op = ov;
}

// ---------------------------------------------------------------------------
// kernel_launch
// inputs: [0] user_emb f32 [100000*64], [1] item_emb f32 [50000*64],
//         [2] edge_index int32 [2 * 1200000]
// output: f32 [150000*64]
// ---------------------------------------------------------------------------
extern "C" void kernel_launch(void* const* d_in, const int* in_sizes, int n_in,
                              void* d_out, int out_size) {
    const float* user_emb = (const float*)d_in[0];
    const float* item_emb = (const float*)d_in[1];
    const int*   edge     = (const int*)d_in[2];
    float*       out      = (float*)d_out;

    const int nu_elems = in_sizes[0];
    const int ni_elems = in_sizes[1];
    const int E        = in_sizes[2] / 2;
    const int N        = nu_elems / DIM + ni_elems / DIM;
    const int total    = N * DIM;

    const int TB = 256;
    const int nblk  = (N + TB - 1) / TB;
    const int eblk  = (E + TB - 1) / TB;
    const int tblk  = (total + TB - 1) / TB;
    const int pullb = (N * 16 + TB - 1) / TB;
    const int scanb = (N + SCAN_CHUNK - 1) / SCAN_CHUNK;

    // CSR build (by destination)
    zero_counts_kernel<<<nblk, TB>>>(N);
    count_kernel<<<eblk, TB>>>(edge, E);
    dinv_kernel<<<nblk, TB>>>(N);
    scan_partial_kernel<<<scanb, SCAN_TB>>>(N);
    scan_blocksums_kernel<<<1, MAX_SCAN_BLOCKS>>>(scanb, N, E);
    scan_write_kernel<<<scanb, SCAN_TB>>>(N);
    fill_kernel<<<eblk, TB>>>(edge, E);

    // x0 and pooled output init
    init_kernel<<<tblk, TB>>>(user_emb, item_emb, nu_elems, total, out);

    // 3 propagation layers, out accumulation fused
    pull_kernel<true ><<<pullb, TB>>>(N, out);   // A -> B
    pull_kernel<false><<<pullb, TB>>>(N, out);   // B -> A
    pull_kernel<true ><<<pullb, TB>>>(N, out);   // A -> B
}

// round 5
// speedup vs baseline: 2.3132x; 1.3603x over previous
#include <cuda_runtime.h>
#include <stdint.h>

#define DIM   64
#define MAX_N 150016           // 100000 users + 50000 items, padded
#define MAX_E 1300000          // actual E = 1,200,000 (incl. flipped copy)

#define SCAN_TB    256
#define SCAN_ITEMS 8           // 2048 elements per block
#define SCAN_CHUNK (SCAN_TB * SCAN_ITEMS)
#define MAX_SCAN_BLOCKS 512

// ---------------------------------------------------------------------------
// Scratch: __device__ globals only (no allocations allowed anywhere).
// ---------------------------------------------------------------------------
__device__ float  g_bufA[MAX_N * DIM];   // ping (holds w = dinv .* x)
__device__ float  g_bufB[MAX_N * DIM];   // pong
__device__ float2 g_dinvs[MAX_N];        // (dinv, dinv^2); 0 on isolated nodes
__device__ int    g_counts[MAX_N];       // in-degree histogram
__device__ int    g_offsets[MAX_N + 1];  // CSR row pointers (by dst)
__device__ int    g_pos[MAX_N];          // scatter cursors
__device__ int    g_src[MAX_E];          // CSR: source node per slot
__device__ int    g_blocksums[MAX_SCAN_BLOCKS];
__device__ int    g_blockoffs[MAX_SCAN_BLOCKS];

// ---------------------------------------------------------------------------
// 1) histogram of destinations
// ---------------------------------------------------------------------------
__global__ void zero_counts_kernel(int n) {
    int i = blockIdx.x * blockDim.x + threadIdx.x;
    if (i < n) g_counts[i] = 0;
}

__global__ void count_kernel(const int* __restrict__ edge, int E) {
    int e = blockIdx.x * blockDim.x + threadIdx.x;
    if (e < E) atomicAdd(&g_counts[edge[E + e]], 1);
}

// deg^{-1/2} and deg^{-1}. Isolated nodes get 0 (never gathered; avoids inf*0=NaN
// in the factored epilogue — matches reference, where norm is only read on edges).
__global__ void dinv_kernel(int n) {
    int i = blockIdx.x * blockDim.x + threadIdx.x;
    if (i < n) {
        int c = g_counts[i];
        float d = (c > 0) ? rsqrtf((float)c) : 0.0f;
        g_dinvs[i] = make_float2(d, d * d);
    }
}

// ---------------------------------------------------------------------------
// 2) multi-block exclusive scan of counts -> offsets (3 phases)
// ---------------------------------------------------------------------------
__global__ __launch_bounds__(SCAN_TB)
void scan_partial_kernel(int n) {
    __shared__ int warp_sums[SCAN_TB / 32];
    const int base = blockIdx.x * SCAN_CHUNK;
    const int t = threadIdx.x;

    int s = 0;
    #pragma unroll
    for (int i = 0; i < SCAN_ITEMS; i++) {
        int idx = base + i * SCAN_TB + t;       // coalesced
        if (idx < n) s += g_counts[idx];
    }
    #pragma unroll
    for (int o = 16; o > 0; o >>= 1) s += __shfl_down_sync(0xffffffffu, s, o);
    if ((t & 31) == 0) warp_sums[t >> 5] = s;
    __syncthreads();
    if (t < SCAN_TB / 32) {
        int v = warp_sums[t];
        #pragma unroll
        for (int o = SCAN_TB / 64; o > 0; o >>= 1) v += __shfl_down_sync(0xffffffffu, v, o);
        if (t == 0) g_blocksums[blockIdx.x] = v;
    }
}

__global__ __launch_bounds__(MAX_SCAN_BLOCKS)
void scan_blocksums_kernel(int nb, int n, int E) {
    __shared__ int sh[MAX_SCAN_BLOCKS];
    const int t = threadIdx.x;
    sh[t] = (t < nb) ? g_blocksums[t] : 0;
    __syncthreads();
    #pragma unroll
    for (int off = 1; off < MAX_SCAN_BLOCKS; off <<= 1) {
        int v = (t >= off) ? sh[t - off] : 0;
        __syncthreads();
        sh[t] += v;
        __syncthreads();
    }
    if (t < nb) g_blockoffs[t] = (t == 0) ? 0 : sh[t - 1];
    if (t == 0) g_offsets[n] = E;
}

__global__ __launch_bounds__(SCAN_TB)
void scan_write_kernel(int n) {
    __shared__ int thread_sums[SCAN_TB];
    const int base = blockIdx.x * SCAN_CHUNK;
    const int t = threadIdx.x;
    const int lo = base + t * SCAN_ITEMS;

    int c[SCAN_ITEMS];
    int s = 0;
    #pragma unroll
    for (int i = 0; i < SCAN_ITEMS; i++) {
        int idx = lo + i;
        c[i] = (idx < n) ? g_counts[idx] : 0;
        s += c[i];
    }
    thread_sums[t] = s;
    __syncthreads();
    #pragma unroll
    for (int off = 1; off < SCAN_TB; off <<= 1) {
        int v = (t >= off) ? thread_sums[t - off] : 0;
        __syncthreads();
        thread_sums[t] += v;
        __syncthreads();
    }
    int prefix = g_blockoffs[blockIdx.x] + ((t == 0) ? 0 : thread_sums[t - 1]);
    #pragma unroll
    for (int i = 0; i < SCAN_ITEMS; i++) {
        int idx = lo + i;
        if (idx < n) {
            g_offsets[idx] = prefix;
            g_pos[idx]     = prefix;
            prefix += c[i];
        }
    }
}

// ---------------------------------------------------------------------------
// 3) scatter edges into CSR slots (source index only — no norm needed)
// ---------------------------------------------------------------------------
__global__ void fill_kernel(const int* __restrict__ edge, int E) {
    int e = blockIdx.x * blockDim.x + threadIdx.x;
    if (e >= E) return;
    int r = edge[e];
    int c = edge[E + e];
    int slot = atomicAdd(&g_pos[c], 1);
    g_src[slot] = r;
}

// ---------------------------------------------------------------------------
// 4) init: out = 0.25 * x0;  A = w0 = dinv .* x0
// ---------------------------------------------------------------------------
__global__ void init_kernel(const float* __restrict__ ue, const float* __restrict__ ie,
                            int nu_elems, int total, float* __restrict__ out) {
    int i = blockIdx.x * blockDim.x + threadIdx.x;
    if (i < total) {
        float v = (i < nu_elems) ? ue[i] : ie[i - nu_elems];
        out[i]    = 0.25f * v;
        g_bufA[i] = v * g_dinvs[i >> 6].x;
    }
}

// ---------------------------------------------------------------------------
// 5) pull pass: S[n] = sum_{k in csr(n)} W[src[k]]   (pure adds, no per-edge norm)
//    out[n] += 0.25 * dinv[n]   * S[n]
//    Y[n]   =        dinv[n]^2 * S[n]   (skipped on last layer)
//    16 threads (half-warp) per node, one float4 lane each; 2-edge unroll with
//    dual accumulators for 2 gathers in flight per thread.
// ---------------------------------------------------------------------------
template <bool A_TO_B, bool LAST>
__global__ __launch_bounds__(256)
void pull_kernel(int N, float* __restrict__ out) {
    int t = blockIdx.x * blockDim.x + threadIdx.x;
    int node = t >> 4;
    if (node >= N) return;
    int c = (t & 15) << 2;

    const float* __restrict__ X = A_TO_B ? g_bufA : g_bufB;
    float*       __restrict__ Y = A_TO_B ? g_bufB : g_bufA;

    const int beg = g_offsets[node];
    const int end = g_offsets[node + 1];

    float a0x = 0.f, a0y = 0.f, a0z = 0.f, a0w = 0.f;
    float a1x = 0.f, a1y = 0.f, a1z = 0.f, a1w = 0.f;

    int k = beg;
    for (; k + 1 < end; k += 2) {
        int s0 = g_src[k];
        int s1 = g_src[k + 1];
        float4 v0 = *reinterpret_cast<const float4*>(X + (size_t)s0 * DIM + c);
        float4 v1 = *reinterpret_cast<const float4*>(X + (size_t)s1 * DIM + c);
        a0x += v0.x; a0y += v0.y; a0z += v0.z; a0w += v0.w;
        a1x += v1.x; a1y += v1.y; a1z += v1.z; a1w += v1.w;
    }
    if (k < end) {
        int s0 = g_src[k];
        float4 v0 = *reinterpret_cast<const float4*>(X + (size_t)s0 * DIM + c);
        a0x += v0.x; a0y += v0.y; a0z += v0.z; a0w += v0.w;
    }

    float sx = a0x + a1x, sy = a0y + a1y, sz = a0z + a1z, sw = a0w + a1w;

    float2 dv = g_dinvs[node];          // (dinv, dinv^2); 0 on isolated nodes
    float e = 0.25f * dv.x;

    float4* op = reinterpret_cast<float4*>(out + (size_t)node * DIM + c);
    float4 ov = *op;
    ov.x = fmaf(e, sx, ov.x);
    ov.y = fmaf(e, sy, ov.y);
    ov.z = fmaf(e, sz, ov.z);
    ov.w = fmaf(e, sw, ov.w);
    *op = ov;

    if (!LAST) {
        float4 r;
        r.x = dv.y * sx; r.y = dv.y * sy; r.z = dv.y * sz; r.w = dv.y * sw;
        *reinterpret_cast<float4*>(Y + (size_t)node * DIM + c) = r;
    }
}

// ---------------------------------------------------------------------------
// kernel_launch
// inputs: [0] user_emb f32 [100000*64], [1] item_emb f32 [50000*64],
//         [2] edge_index int32 [2 * 1200000]
// output: f32 [150000*64]
// ---------------------------------------------------------------------------
extern "C" void kernel_launch(void* const* d_in, const int* in_sizes, int n_in,
                              void* d_out, int out_size) {
    const float* user_emb = (const float*)d_in[0];
    const float* item_emb = (const float*)d_in[1];
    const int*   edge     = (const int*)d_in[2];
    float*       out      = (float*)d_out;

    const int nu_elems = in_sizes[0];
    const int ni_elems = in_sizes[1];
    const int E        = in_sizes[2] / 2;
    const int N        = nu_elems / DIM + ni_elems / DIM;
    const int total    = N * DIM;

    const int TB = 256;
    const int nblk  = (N + TB - 1) / TB;
    const int eblk  = (E + TB - 1) / TB;
    const int tblk  = (total + TB - 1) / TB;
    const int pullb = (N * 16 + TB - 1) / TB;
    const int scanb = (N + SCAN_CHUNK - 1) / SCAN_CHUNK;

    // CSR build (by destination)
    zero_counts_kernel<<<nblk, TB>>>(N);
    count_kernel<<<eblk, TB>>>(edge, E);
    dinv_kernel<<<nblk, TB>>>(N);
    scan_partial_kernel<<<scanb, SCAN_TB>>>(N);
    scan_blocksums_kernel<<<1, MAX_SCAN_BLOCKS>>>(scanb, N, E);
    scan_write_kernel<<<scanb, SCAN_TB>>>(N);
    fill_kernel<<<eblk, TB>>>(edge, E);

    // x0 / w0 and pooled output init
    init_kernel<<<tblk, TB>>>(user_emb, item_emb, nu_elems, total, out);

    // 3 propagation layers, out accumulation fused; last layer skips Y write
    pull_kernel<true , false><<<pullb, TB>>>(N, out);   // A -> B
    pull_kernel<false, false><<<pullb, TB>>>(N, out);   // B -> A
    pull_kernel<true , true ><<<pullb, TB>>>(N, out);   // A -> (discard)
}